// round 14
// baseline (speedup 1.0000x reference)
#include <cuda_runtime.h>

// Quintic Hermite spline, sub-interval cubic table (M=6), gather-pipelined.
// Inputs: x_new [N] f32, knots [nk] f32, function_values [3*nk] f32.
// Output: [N] f32.
//
// Per bin a Chebyshev-economized cubic in sigma = M*(s-i)-(jj+0.5), one
// LDS.128 per query. The loop is software-pipelined at the GATHER level:
// iteration i issues the LDS for iteration i+1 and evaluates iteration i
// from registers, giving the 29-cycle LDS latency a full loop body of cover.
// 896-thread blocks x 2/SM: 1792 thr/SM, 36-reg budget (no spills).

#define M_SUB 6

__global__ void __launch_bounds__(896, 2) quintic_spline_kernel(
    const float* __restrict__ x,
    const float* __restrict__ knots,
    const float* __restrict__ fv,
    float* __restrict__ out,
    int n, int nk)
{
    extern __shared__ float4 T[];   // (nk-1)*M_SUB entries: {b3, b2, b1, b0}

    const float k0f = knots[0];
    const float scalef = (float)(nk - 1) / (knots[nk - 1] - k0f);

    // ---- build sub-interval cubic table ----
    for (int i = threadIdx.x; i < nk - 1; i += blockDim.x) {
        float xl = knots[i];
        float h  = knots[i + 1] - xl;
        float yl   = fv[i],          yr   = fv[i + 1];
        float dyl  = fv[nk + i],     dyr  = fv[nk + i + 1];
        float ddyl = fv[2 * nk + i], ddyr = fv[2 * nk + i + 1];

        float dY = yr - yl;
        float h2 = 0.5f * h * h;
        float c5 =   6.0f * dY - 3.0f * h * (dyl + dyr)               + h2 * (ddyr - ddyl);
        float c4 = -15.0f * dY + h * (8.0f * dyl + 7.0f * dyr)        - h2 * (2.0f * ddyr - 3.0f * ddyl);
        float c3 =  10.0f * dY - 2.0f * h * (3.0f * dyl + 2.0f * dyr) + h2 * (ddyr - 3.0f * ddyl);
        float c2 = h2 * ddyl;
        float c1 = h * dyl;
        float c0 = yl;

        // recompose in tau = s - i:  t = (tau - delta) * nu
        float nu = 1.0f / (h * scalef);
        double delta_d = (double)(xl - k0f) * (double)scalef - (double)i;
        float cc = (float)(-delta_d);

        float a0 = c0;
        float a1 = c1 * nu;
        float nup = nu * nu;
        float a2 = c2 * nup;
        nup *= nu;
        float a3 = c3 * nup;
        nup *= nu;
        float a4 = c4 * nup;
        nup *= nu;
        float a5 = c5 * nup;

        // Taylor shift by -delta -> coefficients of poly in tau
        a4 += cc * a5; a3 += cc * a4; a2 += cc * a3; a1 += cc * a2; a0 += cc * a1;
        a4 += cc * a5; a3 += cc * a4; a2 += cc * a3; a1 += cc * a2;
        a4 += cc * a5; a3 += cc * a4; a2 += cc * a3;
        a4 += cc * a5; a3 += cc * a4;
        a4 += cc * a5;

        const float invM  = 1.0f / (float)M_SUB;
        const float invM2 = invM * invM;
        const float invM3 = invM2 * invM;
        const float invM4 = invM2 * invM2;
        const float invM5 = invM4 * invM;

        #pragma unroll
        for (int jj = 0; jj < M_SUB; jj++) {
            float t0 = (jj + 0.5f) * invM;   // bin center in tau

            float d0 = a0, d1 = a1, d2 = a2, d3 = a3, d4 = a4, d5 = a5;
            d4 += t0 * d5; d3 += t0 * d4; d2 += t0 * d3; d1 += t0 * d2; d0 += t0 * d1;
            d4 += t0 * d5; d3 += t0 * d4; d2 += t0 * d3; d1 += t0 * d2;
            d4 += t0 * d5; d3 += t0 * d4; d2 += t0 * d3;
            d4 += t0 * d5; d3 += t0 * d4;
            d4 += t0 * d5;

            float b0 = d0;
            float b1 = d1 * invM;
            float b2 = d2 * invM2;
            float b3 = d3 * invM3;
            float b4 = d4 * invM4;
            float b5 = d5 * invM5;

            // Chebyshev economization over [-1/2, 1/2]
            b2 += b4 * 0.25f;
            b0 -= b4 * 0.0078125f;
            b3 += b5 * 0.3125f;
            b1 -= b5 * 0.01953125f;

            T[i * M_SUB + jj] = make_float4(b3, b2, b1, b0);
        }
    }
    __syncthreads();

    const float scaleM = scalef * (float)M_SUB;
    const int jmax = (nk - 1) * M_SUB - 1;

    const int n2 = n >> 1;
    const int stride = gridDim.x * blockDim.x;
    int i2 = blockIdx.x * blockDim.x + threadIdx.x;

    if (i2 < n2) {
        // ---- pipeline prologue: stage 0 gathers ----
        float2 xv = reinterpret_cast<const float2*>(x)[i2];
        float s0 = (xv.x - k0f) * scaleM;
        float s1 = (xv.y - k0f) * scaleM;
        int j0 = max(0, min((int)s0, jmax));
        int j1 = max(0, min((int)s1, jmax));
        float g0 = s0 - (float)j0 - 0.5f;
        float g1 = s1 - (float)j1 - 0.5f;
        float4 q0 = T[j0];
        float4 q1 = T[j1];

        while (true) {
            int inext = i2 + stride;
            bool have_next = (inext < n2);

            float4 qn0, qn1;
            float gn0, gn1;
            if (have_next) {
                // issue next iteration's load + gathers BEFORE consuming
                float2 xn = reinterpret_cast<const float2*>(x)[inext];
                float sn0 = (xn.x - k0f) * scaleM;
                float sn1 = (xn.y - k0f) * scaleM;
                int jn0 = max(0, min((int)sn0, jmax));
                int jn1 = max(0, min((int)sn1, jmax));
                gn0 = sn0 - (float)jn0 - 0.5f;
                gn1 = sn1 - (float)jn1 - 0.5f;
                qn0 = T[jn0];
                qn1 = T[jn1];
            }

            // evaluate current iteration (q/g loaded one iteration ago)
            float v0 = q0.x, v1 = q1.x;
            v0 = v0 * g0 + q0.y;  v1 = v1 * g1 + q1.y;
            v0 = v0 * g0 + q0.z;  v1 = v1 * g1 + q1.z;
            v0 = v0 * g0 + q0.w;  v1 = v1 * g1 + q1.w;
            reinterpret_cast<float2*>(out)[i2] = make_float2(v0, v1);

            if (!have_next) break;
            q0 = qn0; q1 = qn1; g0 = gn0; g1 = gn1;
            i2 = inext;
        }
    }

    // tail (n odd)
    if ((n & 1) && (blockIdx.x == 0) && (threadIdx.x == 0)) {
        float xq = x[n - 1];
        float s = (xq - k0f) * scaleM;
        int j = max(0, min((int)s, jmax));
        float g = s - (float)j - 0.5f;
        float4 q = T[j];
        float v = q.x;
        v = v * g + q.y;
        v = v * g + q.z;
        v = v * g + q.w;
        out[n - 1] = v;
    }
}

extern "C" void kernel_launch(void* const* d_in, const int* in_sizes, int n_in,
                              void* d_out, int out_size)
{
    const float* x     = (const float*)d_in[0];
    const float* knots = (const float*)d_in[1];
    const float* fv    = (const float*)d_in[2];
    float* out = (float*)d_out;

    int n  = in_sizes[0];
    int nk = in_sizes[1];

    size_t smem_bytes = (size_t)(nk - 1) * M_SUB * sizeof(float4);  // ~98 KB @ nk=1024

    cudaFuncSetAttribute(quintic_spline_kernel,
                         cudaFuncAttributeMaxDynamicSharedMemorySize, (int)smem_bytes);
    cudaFuncSetAttribute(quintic_spline_kernel,
                         cudaFuncAttributePreferredSharedMemoryCarveout, 100);

    const int threads = 896;
    int n2 = (n + 1) >> 1;
    int blocks = (n2 + threads - 1) / threads;
    int cap = 148 * 2;  // two 896-thread blocks per SM (1792 thr/SM)
    if (blocks > cap) blocks = cap;
    if (blocks < 1) blocks = 1;

    quintic_spline_kernel<<<blocks, threads, smem_bytes>>>(x, knots, fv, out, n, nk);
}

// round 15
// speedup vs baseline: 1.0652x; 1.0652x over previous
#include <cuda_runtime.h>

// Quintic Hermite spline, sub-interval cubic table (M=6).
// Inputs: x_new [N] f32, knots [nk] f32, function_values [3*nk] f32.
// Output: [N] f32.
//
// Chebyshev-economized cubic per bin, sigma = M*(s-i)-(jj+0.5), one LDS.128
// per query. Shape: 768-thread blocks x 2/SM (1536 thr, 75% occ) with
// 4 queries/thread so each warp keeps 4 gathers in flight — combines the
// occupancy of round 13 with the gather MLP of round 12.

#define M_SUB 6

__global__ void __launch_bounds__(768, 2) quintic_spline_kernel(
    const float* __restrict__ x,
    const float* __restrict__ knots,
    const float* __restrict__ fv,
    float* __restrict__ out,
    int n, int nk)
{
    extern __shared__ float4 T[];   // (nk-1)*M_SUB entries: {b3, b2, b1, b0}

    const float k0f = knots[0];
    const float scalef = (float)(nk - 1) / (knots[nk - 1] - k0f);

    // ---- build sub-interval cubic table ----
    for (int i = threadIdx.x; i < nk - 1; i += blockDim.x) {
        float xl = knots[i];
        float h  = knots[i + 1] - xl;
        float yl   = fv[i],          yr   = fv[i + 1];
        float dyl  = fv[nk + i],     dyr  = fv[nk + i + 1];
        float ddyl = fv[2 * nk + i], ddyr = fv[2 * nk + i + 1];

        float dY = yr - yl;
        float h2 = 0.5f * h * h;
        float c5 =   6.0f * dY - 3.0f * h * (dyl + dyr)               + h2 * (ddyr - ddyl);
        float c4 = -15.0f * dY + h * (8.0f * dyl + 7.0f * dyr)        - h2 * (2.0f * ddyr - 3.0f * ddyl);
        float c3 =  10.0f * dY - 2.0f * h * (3.0f * dyl + 2.0f * dyr) + h2 * (ddyr - 3.0f * ddyl);
        float c2 = h2 * ddyl;
        float c1 = h * dyl;
        float c0 = yl;

        // recompose in tau = s - i:  t = (tau - delta) * nu
        float nu = 1.0f / (h * scalef);
        double delta_d = (double)(xl - k0f) * (double)scalef - (double)i;
        float cc = (float)(-delta_d);

        float a0 = c0;
        float a1 = c1 * nu;
        float nup = nu * nu;
        float a2 = c2 * nup;
        nup *= nu;
        float a3 = c3 * nup;
        nup *= nu;
        float a4 = c4 * nup;
        nup *= nu;
        float a5 = c5 * nup;

        // Taylor shift by -delta -> coefficients of poly in tau
        a4 += cc * a5; a3 += cc * a4; a2 += cc * a3; a1 += cc * a2; a0 += cc * a1;
        a4 += cc * a5; a3 += cc * a4; a2 += cc * a3; a1 += cc * a2;
        a4 += cc * a5; a3 += cc * a4; a2 += cc * a3;
        a4 += cc * a5; a3 += cc * a4;
        a4 += cc * a5;

        const float invM  = 1.0f / (float)M_SUB;
        const float invM2 = invM * invM;
        const float invM3 = invM2 * invM;
        const float invM4 = invM2 * invM2;
        const float invM5 = invM4 * invM;

        #pragma unroll
        for (int jj = 0; jj < M_SUB; jj++) {
            float t0 = (jj + 0.5f) * invM;   // bin center in tau

            float d0 = a0, d1 = a1, d2 = a2, d3 = a3, d4 = a4, d5 = a5;
            d4 += t0 * d5; d3 += t0 * d4; d2 += t0 * d3; d1 += t0 * d2; d0 += t0 * d1;
            d4 += t0 * d5; d3 += t0 * d4; d2 += t0 * d3; d1 += t0 * d2;
            d4 += t0 * d5; d3 += t0 * d4; d2 += t0 * d3;
            d4 += t0 * d5; d3 += t0 * d4;
            d4 += t0 * d5;

            float b0 = d0;
            float b1 = d1 * invM;
            float b2 = d2 * invM2;
            float b3 = d3 * invM3;
            float b4 = d4 * invM4;
            float b5 = d5 * invM5;

            // Chebyshev economization over [-1/2, 1/2]:
            // sigma^4 ~ (1/4)sigma^2 - 1/128 ; sigma^5 ~ (5/16)sigma^3 - (5/256)sigma
            b2 += b4 * 0.25f;
            b0 -= b4 * 0.0078125f;
            b3 += b5 * 0.3125f;
            b1 -= b5 * 0.01953125f;

            T[i * M_SUB + jj] = make_float4(b3, b2, b1, b0);
        }
    }
    __syncthreads();

    const float scaleM = scalef * (float)M_SUB;
    const int jmax = (nk - 1) * M_SUB - 1;

    const int n4 = n >> 2;
    const int stride = gridDim.x * blockDim.x;
    int i4 = blockIdx.x * blockDim.x + threadIdx.x;

    for (; i4 < n4; i4 += stride) {
        float4 xv = reinterpret_cast<const float4*>(x)[i4];

        float s0 = (xv.x - k0f) * scaleM;
        float s1 = (xv.y - k0f) * scaleM;
        float s2 = (xv.z - k0f) * scaleM;
        float s3 = (xv.w - k0f) * scaleM;
        int j0 = max(0, min((int)s0, jmax));
        int j1 = max(0, min((int)s1, jmax));
        int j2 = max(0, min((int)s2, jmax));
        int j3 = max(0, min((int)s3, jmax));
        float g0 = s0 - (float)j0 - 0.5f;
        float g1 = s1 - (float)j1 - 0.5f;
        float g2 = s2 - (float)j2 - 0.5f;
        float g3 = s3 - (float)j3 - 0.5f;

        // 4 gathers back-to-back, 4 in flight per thread
        float4 q0 = T[j0];
        float4 q1 = T[j1];
        float4 q2 = T[j2];
        float4 q3 = T[j3];

        float v0 = q0.x, v1 = q1.x, v2 = q2.x, v3 = q3.x;
        v0 = v0 * g0 + q0.y;  v1 = v1 * g1 + q1.y;  v2 = v2 * g2 + q2.y;  v3 = v3 * g3 + q3.y;
        v0 = v0 * g0 + q0.z;  v1 = v1 * g1 + q1.z;  v2 = v2 * g2 + q2.z;  v3 = v3 * g3 + q3.z;
        v0 = v0 * g0 + q0.w;  v1 = v1 * g1 + q1.w;  v2 = v2 * g2 + q2.w;  v3 = v3 * g3 + q3.w;

        reinterpret_cast<float4*>(out)[i4] = make_float4(v0, v1, v2, v3);
    }

    // tail (n not divisible by 4)
    int tail = n & 3;
    int base = n4 << 2;
    int gid = blockIdx.x * blockDim.x + threadIdx.x;
    if (gid < tail) {
        float xq = x[base + gid];
        float s = (xq - k0f) * scaleM;
        int j = max(0, min((int)s, jmax));
        float g = s - (float)j - 0.5f;
        float4 q = T[j];
        float v = q.x;
        v = v * g + q.y;
        v = v * g + q.z;
        v = v * g + q.w;
        out[base + gid] = v;
    }
}

extern "C" void kernel_launch(void* const* d_in, const int* in_sizes, int n_in,
                              void* d_out, int out_size)
{
    const float* x     = (const float*)d_in[0];
    const float* knots = (const float*)d_in[1];
    const float* fv    = (const float*)d_in[2];
    float* out = (float*)d_out;

    int n  = in_sizes[0];
    int nk = in_sizes[1];

    size_t smem_bytes = (size_t)(nk - 1) * M_SUB * sizeof(float4);  // ~98 KB @ nk=1024

    cudaFuncSetAttribute(quintic_spline_kernel,
                         cudaFuncAttributeMaxDynamicSharedMemorySize, (int)smem_bytes);
    cudaFuncSetAttribute(quintic_spline_kernel,
                         cudaFuncAttributePreferredSharedMemoryCarveout, 100);

    const int threads = 768;
    int n4 = (n + 3) >> 2;
    int blocks = (n4 + threads - 1) / threads;
    int cap = 148 * 2;  // two 768-thread blocks per SM (1536 thr/SM, 75% occ)
    if (blocks > cap) blocks = cap;
    if (blocks < 1) blocks = 1;

    quintic_spline_kernel<<<blocks, threads, smem_bytes>>>(x, knots, fv, out, n, nk);
}

// round 16
// speedup vs baseline: 1.0662x; 1.0009x over previous
#include <cuda_runtime.h>

// Quintic Hermite spline, sub-interval cubic table (M=6).
// Inputs: x_new [N] f32, knots [nk] f32, function_values [3*nk] f32.
// Output: [N] f32.
//
// Chebyshev-economized cubic per bin, sigma = M*(s-i)-(jj+0.5), one LDS.128
// per query. 768-thread blocks x 2/SM (1536 thr), 4 queries/thread.
// Streaming cache hints (__ldcs/__stcs) keep the touch-once x/out streams
// from polluting L2.

#define M_SUB 6

__global__ void __launch_bounds__(768, 2) quintic_spline_kernel(
    const float* __restrict__ x,
    const float* __restrict__ knots,
    const float* __restrict__ fv,
    float* __restrict__ out,
    int n, int nk)
{
    extern __shared__ float4 T[];   // (nk-1)*M_SUB entries: {b3, b2, b1, b0}

    const float k0f = knots[0];
    const float scalef = (float)(nk - 1) / (knots[nk - 1] - k0f);

    // ---- build sub-interval cubic table ----
    for (int i = threadIdx.x; i < nk - 1; i += blockDim.x) {
        float xl = knots[i];
        float h  = knots[i + 1] - xl;
        float yl   = fv[i],          yr   = fv[i + 1];
        float dyl  = fv[nk + i],     dyr  = fv[nk + i + 1];
        float ddyl = fv[2 * nk + i], ddyr = fv[2 * nk + i + 1];

        float dY = yr - yl;
        float h2 = 0.5f * h * h;
        float c5 =   6.0f * dY - 3.0f * h * (dyl + dyr)               + h2 * (ddyr - ddyl);
        float c4 = -15.0f * dY + h * (8.0f * dyl + 7.0f * dyr)        - h2 * (2.0f * ddyr - 3.0f * ddyl);
        float c3 =  10.0f * dY - 2.0f * h * (3.0f * dyl + 2.0f * dyr) + h2 * (ddyr - 3.0f * ddyl);
        float c2 = h2 * ddyl;
        float c1 = h * dyl;
        float c0 = yl;

        // recompose in tau = s - i:  t = (tau - delta) * nu
        float nu = 1.0f / (h * scalef);
        double delta_d = (double)(xl - k0f) * (double)scalef - (double)i;
        float cc = (float)(-delta_d);

        float a0 = c0;
        float a1 = c1 * nu;
        float nup = nu * nu;
        float a2 = c2 * nup;
        nup *= nu;
        float a3 = c3 * nup;
        nup *= nu;
        float a4 = c4 * nup;
        nup *= nu;
        float a5 = c5 * nup;

        // Taylor shift by -delta -> coefficients of poly in tau
        a4 += cc * a5; a3 += cc * a4; a2 += cc * a3; a1 += cc * a2; a0 += cc * a1;
        a4 += cc * a5; a3 += cc * a4; a2 += cc * a3; a1 += cc * a2;
        a4 += cc * a5; a3 += cc * a4; a2 += cc * a3;
        a4 += cc * a5; a3 += cc * a4;
        a4 += cc * a5;

        const float invM  = 1.0f / (float)M_SUB;
        const float invM2 = invM * invM;
        const float invM3 = invM2 * invM;
        const float invM4 = invM2 * invM2;
        const float invM5 = invM4 * invM;

        #pragma unroll
        for (int jj = 0; jj < M_SUB; jj++) {
            float t0 = (jj + 0.5f) * invM;   // bin center in tau

            float d0 = a0, d1 = a1, d2 = a2, d3 = a3, d4 = a4, d5 = a5;
            d4 += t0 * d5; d3 += t0 * d4; d2 += t0 * d3; d1 += t0 * d2; d0 += t0 * d1;
            d4 += t0 * d5; d3 += t0 * d4; d2 += t0 * d3; d1 += t0 * d2;
            d4 += t0 * d5; d3 += t0 * d4; d2 += t0 * d3;
            d4 += t0 * d5; d3 += t0 * d4;
            d4 += t0 * d5;

            float b0 = d0;
            float b1 = d1 * invM;
            float b2 = d2 * invM2;
            float b3 = d3 * invM3;
            float b4 = d4 * invM4;
            float b5 = d5 * invM5;

            // Chebyshev economization over [-1/2, 1/2]:
            // sigma^4 ~ (1/4)sigma^2 - 1/128 ; sigma^5 ~ (5/16)sigma^3 - (5/256)sigma
            b2 += b4 * 0.25f;
            b0 -= b4 * 0.0078125f;
            b3 += b5 * 0.3125f;
            b1 -= b5 * 0.01953125f;

            T[i * M_SUB + jj] = make_float4(b3, b2, b1, b0);
        }
    }
    __syncthreads();

    const float scaleM = scalef * (float)M_SUB;
    const int jmax = (nk - 1) * M_SUB - 1;

    const int n4 = n >> 2;
    const int stride = gridDim.x * blockDim.x;
    int i4 = blockIdx.x * blockDim.x + threadIdx.x;

    for (; i4 < n4; i4 += stride) {
        // streaming (evict-first) load of the touch-once x stream
        float4 xv = __ldcs(reinterpret_cast<const float4*>(x) + i4);

        float s0 = (xv.x - k0f) * scaleM;
        float s1 = (xv.y - k0f) * scaleM;
        float s2 = (xv.z - k0f) * scaleM;
        float s3 = (xv.w - k0f) * scaleM;
        int j0 = max(0, min((int)s0, jmax));
        int j1 = max(0, min((int)s1, jmax));
        int j2 = max(0, min((int)s2, jmax));
        int j3 = max(0, min((int)s3, jmax));
        float g0 = s0 - (float)j0 - 0.5f;
        float g1 = s1 - (float)j1 - 0.5f;
        float g2 = s2 - (float)j2 - 0.5f;
        float g3 = s3 - (float)j3 - 0.5f;

        // 4 gathers back-to-back, 4 in flight per thread
        float4 q0 = T[j0];
        float4 q1 = T[j1];
        float4 q2 = T[j2];
        float4 q3 = T[j3];

        float v0 = q0.x, v1 = q1.x, v2 = q2.x, v3 = q3.x;
        v0 = v0 * g0 + q0.y;  v1 = v1 * g1 + q1.y;  v2 = v2 * g2 + q2.y;  v3 = v3 * g3 + q3.y;
        v0 = v0 * g0 + q0.z;  v1 = v1 * g1 + q1.z;  v2 = v2 * g2 + q2.z;  v3 = v3 * g3 + q3.z;
        v0 = v0 * g0 + q0.w;  v1 = v1 * g1 + q1.w;  v2 = v2 * g2 + q2.w;  v3 = v3 * g3 + q3.w;

        // streaming store of the touch-once out stream
        __stcs(reinterpret_cast<float4*>(out) + i4, make_float4(v0, v1, v2, v3));
    }

    // tail (n not divisible by 4)
    int tail = n & 3;
    int base = n4 << 2;
    int gid = blockIdx.x * blockDim.x + threadIdx.x;
    if (gid < tail) {
        float xq = x[base + gid];
        float s = (xq - k0f) * scaleM;
        int j = max(0, min((int)s, jmax));
        float g = s - (float)j - 0.5f;
        float4 q = T[j];
        float v = q.x;
        v = v * g + q.y;
        v = v * g + q.z;
        v = v * g + q.w;
        out[base + gid] = v;
    }
}

extern "C" void kernel_launch(void* const* d_in, const int* in_sizes, int n_in,
                              void* d_out, int out_size)
{
    const float* x     = (const float*)d_in[0];
    const float* knots = (const float*)d_in[1];
    const float* fv    = (const float*)d_in[2];
    float* out = (float*)d_out;

    int n  = in_sizes[0];
    int nk = in_sizes[1];

    size_t smem_bytes = (size_t)(nk - 1) * M_SUB * sizeof(float4);  // ~98 KB @ nk=1024

    cudaFuncSetAttribute(quintic_spline_kernel,
                         cudaFuncAttributeMaxDynamicSharedMemorySize, (int)smem_bytes);
    cudaFuncSetAttribute(quintic_spline_kernel,
                         cudaFuncAttributePreferredSharedMemoryCarveout, 100);

    const int threads = 768;
    int n4 = (n + 3) >> 2;
    int blocks = (n4 + threads - 1) / threads;
    int cap = 148 * 2;  // two 768-thread blocks per SM (1536 thr/SM)
    if (blocks > cap) blocks = cap;
    if (blocks < 1) blocks = 1;

    quintic_spline_kernel<<<blocks, threads, smem_bytes>>>(x, knots, fv, out, n, nk);
}